// round 16
// baseline (speedup 1.0000x reference)
#include <cuda_runtime.h>
#include <cuda_fp16.h>
#include <cstdint>
#include <math.h>

// B=32, N1=2048, DIM=1024, HEADS=16, DH=64, NQ=64, L=2, FF=4096
#define F_RES  1
#define F_GELU 4
#define F_HALF 8
#define F_BOTH 16

// ---- scratch (device globals; allocation-free rule) ----
__device__ __half g_z   [67108864];   // 65536 x 1024  unit-LN(x)
__device__ __half g_kvX [268435456];  // 65536 x 4096  (both layers fused)
__device__ float  g_lat [2097152];
__device__ __half g_latH[2097152];
__device__ __half g_ltn [2097152];
__device__ __half g_qkvL[6291456];    // 2048 x 3072  (q | kvL)
__device__ __half g_o   [2097152];
__device__ float  g_t2  [2097152];
__device__ __half g_h   [8388608];    // 2048 x 4096
__device__ __half g_WaT [6291456];    // 2 x [3072][1024]
__device__ __half g_WoT [2097152];
__device__ __half g_prT [1048576];
__device__ __half g_WkvTs[4194304];   // [4096][1024] scaled by norm1_s (2 layers)
__device__ __half g_W1T [8388608];
__device__ __half g_W2T [8388608];
__device__ float  g_bkv [4096];

#define WAT_LSTRIDE 3145728

// ---------------------------------------------------------------------------
__device__ __forceinline__ uint32_t s2u(const void* p) {
    return (uint32_t)__cvta_generic_to_shared(p);
}
__device__ __forceinline__ void cpasync16(uint32_t dst, const void* src) {
    asm volatile("cp.async.cg.shared.global [%0], [%1], 16;" :: "r"(dst), "l"(src) : "memory");
}
// gelu(x) = 0.5x(1+tanh(u)) = x * sigmoid(2u),  u = 0.79788456(x + 0.044715 x^3)
__device__ __forceinline__ float gelu_f(float x) {
    float u = 0.7978845608028654f * (x + 0.044715f * x * x * x);
    return x / (1.0f + __expf(-2.0f * u));
}
#define MMA16816(c, a0, a1, a2, a3, b0, b1) \
    asm volatile( \
        "mma.sync.aligned.m16n8k16.row.col.f32.f16.f16.f32 " \
        "{%0,%1,%2,%3}, {%4,%5,%6,%7}, {%8,%9}, {%0,%1,%2,%3};" \
        : "+f"((c)[0]), "+f"((c)[1]), "+f"((c)[2]), "+f"((c)[3]) \
        : "r"(a0), "r"(a1), "r"(a2), "r"(a3), "r"(b0), "r"(b1))
__device__ __forceinline__ void ldsm_x2_t(uint32_t& r0, uint32_t& r1, uint32_t addr) {
    asm volatile("ldmatrix.sync.aligned.m8n8.x2.trans.shared.b16 {%0,%1}, [%2];"
                 : "=r"(r0), "=r"(r1) : "r"(addr));
}

// ---------------------------------------------------------------------------
// fp16 mma GEMM (frozen config, validated R11/R13/R14):
// BM=128, BN=128, BK=64, 4 warps (2x2), warp tile 64x64, m16n8k16,
// 3-stage cp.async pipeline, 2 CTAs/SM. K % 64 == 0, K >= 192.
// ---------------------------------------------------------------------------
#define AS_H      72
#define TILE_H    (128 * AS_H)
#define STG_H     (2 * TILE_H)
#define SMEM_TC   (3 * STG_H * 2)      // 110592

__device__ __forceinline__ void load_tile(
    __half* sm, int s, const __half* __restrict__ A, const __half* __restrict__ Bt,
    int K, size_t rowBase, size_t colBase, int t, int tid)
{
    __half* As = sm + s * STG_H;
    __half* Bs = As + TILE_H;
    const __half* Ag = A  + rowBase * K + t * 64;
    const __half* Bg = Bt + colBase * K + t * 64;
#pragma unroll
    for (int i = 0; i < 8; i++) {
        int ch = tid + (i << 7);
        int r = ch >> 3, c = ch & 7;
        cpasync16(s2u(As + r * AS_H + c * 8), Ag + (size_t)r * K + c * 8);
    }
#pragma unroll
    for (int i = 0; i < 8; i++) {
        int ch = tid + (i << 7);
        int r = ch >> 3, c = ch & 7;
        cpasync16(s2u(Bs + r * AS_H + c * 8), Bg + (size_t)r * K + c * 8);
    }
    asm volatile("cp.async.commit_group;" ::: "memory");
}

__global__ __launch_bounds__(128, 2) void tc_gemm(
    const __half* __restrict__ A, const __half* __restrict__ Bt,
    const float* __restrict__ Cin, const float* __restrict__ bias,
    float* __restrict__ C, __half* __restrict__ Ch,
    int M, int N, int K, int flags)
{
    extern __shared__ __align__(16) __half sm[];
    const int tid = threadIdx.x, wid = tid >> 5, lane = tid & 31;
    const int wm = wid & 1, wn = wid >> 1;
    const int gid = lane >> 2, tg = lane & 3;
    const size_t rowBase = (size_t)blockIdx.y * 128;
    const size_t colBase = (size_t)blockIdx.x * 128;

    float c[4][8][4];
#pragma unroll
    for (int mi = 0; mi < 4; mi++)
#pragma unroll
        for (int ni = 0; ni < 8; ni++)
#pragma unroll
            for (int k = 0; k < 4; k++) c[mi][ni][k] = 0.f;

    const int KT = K >> 6;
#pragma unroll
    for (int t = 0; t < 2; t++) load_tile(sm, t, A, Bt, K, rowBase, colBase, t, tid);

    for (int t = 0; t < KT; t++) {
        const int s = t % 3;
        asm volatile("cp.async.wait_group 1;" ::: "memory");
        __syncthreads();
        const int tp = t + 2;
        if (tp < KT) load_tile(sm, tp % 3, A, Bt, K, rowBase, colBase, tp, tid);

        const __half* As = sm + s * STG_H;
        const __half* Bs = As + TILE_H;
#pragma unroll
        for (int ks = 0; ks < 4; ks++) {
            const int k0 = ks << 4;
            uint32_t a[4][4], b[8][2];
#pragma unroll
            for (int mi = 0; mi < 4; mi++) {
                const __half* ap = As + (wm * 64 + mi * 16 + gid) * AS_H + k0 + 2 * tg;
                a[mi][0] = *(const uint32_t*)(ap);
                a[mi][1] = *(const uint32_t*)(ap + 8 * AS_H);
                a[mi][2] = *(const uint32_t*)(ap + 8);
                a[mi][3] = *(const uint32_t*)(ap + 8 * AS_H + 8);
            }
#pragma unroll
            for (int ni = 0; ni < 8; ni++) {
                const __half* bp = Bs + (wn * 64 + ni * 8 + gid) * AS_H + k0 + 2 * tg;
                b[ni][0] = *(const uint32_t*)(bp);
                b[ni][1] = *(const uint32_t*)(bp + 8);
            }
#pragma unroll
            for (int mi = 0; mi < 4; mi++)
#pragma unroll
                for (int ni = 0; ni < 8; ni++)
                    MMA16816(c[mi][ni], a[mi][0], a[mi][1], a[mi][2], a[mi][3],
                             b[ni][0], b[ni][1]);
        }
    }

    // epilogue
#pragma unroll
    for (int mi = 0; mi < 4; mi++) {
        const size_t r0 = rowBase + wm * 64 + mi * 16 + gid;
        const size_t r1 = r0 + 8;
#pragma unroll
        for (int ni = 0; ni < 8; ni++) {
            const size_t col = colBase + wn * 64 + ni * 8 + tg * 2;
            float v0 = c[mi][ni][0], v1 = c[mi][ni][1];
            float v2 = c[mi][ni][2], v3 = c[mi][ni][3];
            if (bias) {
                float b0 = bias[col], b1 = bias[col + 1];
                v0 += b0; v1 += b1; v2 += b0; v3 += b1;
            }
            if (flags & F_GELU) {
                v0 = gelu_f(v0); v1 = gelu_f(v1); v2 = gelu_f(v2); v3 = gelu_f(v3);
            }
            if (flags & F_RES) {
                const float2 p0 = *(const float2*)(Cin + r0 * N + col);
                const float2 p1 = *(const float2*)(Cin + r1 * N + col);
                v0 += p0.x; v1 += p0.y; v2 += p1.x; v3 += p1.y;
            }
            if (flags & F_HALF) {
                *(__half2*)(Ch + r0 * N + col) = __floats2half2_rn(v0, v1);
                *(__half2*)(Ch + r1 * N + col) = __floats2half2_rn(v2, v3);
            } else {
                *(float2*)(C + r0 * N + col) = make_float2(v0, v1);
                *(float2*)(C + r1 * N + col) = make_float2(v2, v3);
                if (flags & F_BOTH) {
                    *(__half2*)(Ch + r0 * N + col) = __floats2half2_rn(v0, v1);
                    *(__half2*)(Ch + r1 * N + col) = __floats2half2_rn(v2, v3);
                }
            }
        }
    }
}

// ---------------------------------------------------------------------------
__global__ void bcast_kernel(const float* __restrict__ lat0, float* __restrict__ lat)
{
    int i = blockIdx.x * 256 + threadIdx.x;
    lat[i] = lat0[i & 65535];
}

// ---------------------------------------------------------------------------
// Warp-per-row LayerNorm over 1024 cols. 128 threads = 4 rows/block.
// ---------------------------------------------------------------------------
__global__ __launch_bounds__(128) void lnw_kernel(
    const float* __restrict__ in, float* __restrict__ outF, __half* __restrict__ outH,
    const float* __restrict__ gs, const float* __restrict__ gb)
{
    const int row = blockIdx.x * 4 + (threadIdx.x >> 5);
    const int lane = threadIdx.x & 31;
    const float4* ip = (const float4*)(in + (size_t)row * 1024);

    float4 v[8];
    float s = 0.f, s2 = 0.f;
#pragma unroll
    for (int j = 0; j < 8; j++) {
        v[j] = ip[lane + 32 * j];
        s  += v[j].x + v[j].y + v[j].z + v[j].w;
        s2 += v[j].x*v[j].x + v[j].y*v[j].y + v[j].z*v[j].z + v[j].w*v[j].w;
    }
#pragma unroll
    for (int o = 16; o; o >>= 1) {
        s  += __shfl_xor_sync(0xffffffffu, s,  o);
        s2 += __shfl_xor_sync(0xffffffffu, s2, o);
    }
    const float mean = s * (1.0f / 1024.0f);
    const float inv  = rsqrtf(s2 * (1.0f / 1024.0f) - mean * mean + 1e-5f);

#pragma unroll
    for (int j = 0; j < 8; j++) {
        const int idx = lane + 32 * j;
        float4 ov;
        ov.x = (v[j].x - mean) * inv; ov.y = (v[j].y - mean) * inv;
        ov.z = (v[j].z - mean) * inv; ov.w = (v[j].w - mean) * inv;
        if (gs) {
            const float4 sv = ((const float4*)gs)[idx];
            const float4 bv = ((const float4*)gb)[idx];
            ov.x = ov.x * sv.x + bv.x; ov.y = ov.y * sv.y + bv.y;
            ov.z = ov.z * sv.z + bv.z; ov.w = ov.w * sv.w + bv.w;
        }
        if (outH) {
            __half2 h0 = __floats2half2_rn(ov.x, ov.y);
            __half2 h1 = __floats2half2_rn(ov.z, ov.w);
            uint2 pk;
            pk.x = *(uint32_t*)&h0; pk.y = *(uint32_t*)&h1;
            ((uint2*)(outH + (size_t)row * 1024))[idx] = pk;
        } else {
            ((float4*)(outF + (size_t)row * 1024))[idx] = ov;
        }
    }
}

// ---------------------------------------------------------------------------
// transpose (batched over gridDim.z): in[z][K][N] fp32 -> out half, with
// independent output layer stride (ostride elements per z).
// ---------------------------------------------------------------------------
__global__ void transpose_kernel(const float* __restrict__ in, __half* __restrict__ out,
                                 int K, int N, const float* __restrict__ sc,
                                 size_t ostride)
{
    __shared__ float t[32][33];
    const float* inz = in + (size_t)blockIdx.z * K * N;
    __half* outz = out + (size_t)blockIdx.z * ostride;
    const float* scz = sc ? sc + (size_t)blockIdx.z * K : nullptr;
    int nb = blockIdx.x * 32, kb = blockIdx.y * 32;
    int tx = threadIdx.x, ty = threadIdx.y;
#pragma unroll
    for (int i = 0; i < 4; i++) {
        int k = kb + ty + i * 8;
        float v = inz[(size_t)k * N + nb + tx];
        if (scz) v *= scz[k];
        t[ty + i * 8][tx] = v;
    }
    __syncthreads();
#pragma unroll
    for (int i = 0; i < 4; i++)
        outz[(size_t)(nb + ty + i * 8) * K + kb + tx] = __float2half(t[tx][ty + i * 8]);
}

// ---------------------------------------------------------------------------
// fused Wkv transpose: scaled -> WkvTs, plain -> WaT rows [1024, 3072)
// ---------------------------------------------------------------------------
__global__ void transkv_kernel(const float* __restrict__ in, __half* __restrict__ outS,
                               __half* __restrict__ outP, const float* __restrict__ sc)
{
    __shared__ float t[32][33];
    __shared__ float scs[32];
    const float* inz = in + (size_t)blockIdx.z * 2097152;
    __half* oS = outS + (size_t)blockIdx.z * 2097152;
    __half* oP = outP + (size_t)blockIdx.z * WAT_LSTRIDE + 1024 * 1024;
    int nb = blockIdx.x * 32, kb = blockIdx.y * 32;
    int tx = threadIdx.x, ty = threadIdx.y;
    if (ty == 0) scs[tx] = sc[blockIdx.z * 1024 + kb + tx];
#pragma unroll
    for (int i = 0; i < 4; i++) {
        int k = kb + ty + i * 8;
        t[ty + i * 8][tx] = inz[(size_t)k * 2048 + nb + tx];
    }
    __syncthreads();
#pragma unroll
    for (int i = 0; i < 4; i++) {
        size_t oi = (size_t)(nb + ty + i * 8) * 1024 + kb + tx;
        float v = t[tx][ty + i * 8];
        oP[oi] = __float2half(v);
        oS[oi] = __float2half(v * scs[tx]);
    }
}

// ---------------------------------------------------------------------------
// bias fold from WaT rows [1024,3072)
// ---------------------------------------------------------------------------
__global__ __launch_bounds__(128) void gemv_bias_kernel(
    const float* __restrict__ b, const __half* __restrict__ WaT,
    float* __restrict__ bias)
{
    const int j = blockIdx.x * 4 + (threadIdx.x >> 5);
    const int lane = threadIdx.x & 31;
    const int layer = j >> 11, r = j & 2047;
    const float* bz = b + layer * 1024;
    const __half* wp = WaT + (size_t)layer * WAT_LSTRIDE + (size_t)(1024 + r) * 1024;

    float s = 0.f;
#pragma unroll
    for (int i = 0; i < 4; i++) {
        uint4 w8 = ((const uint4*)wp)[lane + 32 * i];
        const __half2* hw = (const __half2*)&w8;
        const int k0 = (lane + 32 * i) * 8;
#pragma unroll
        for (int p = 0; p < 4; p++) {
            float2 wf = __half22float2(hw[p]);
            s += wf.x * bz[k0 + 2 * p] + wf.y * bz[k0 + 2 * p + 1];
        }
    }
#pragma unroll
    for (int o = 16; o; o >>= 1) s += __shfl_xor_sync(0xffffffffu, s, o);
    if (lane == 0) bias[j] = s;
}

// ---------------------------------------------------------------------------
// Attention (validated R14): cp.async double-buffered K/V + ldmatrix.trans
// ---------------------------------------------------------------------------
#define SMEM_ATT (5 * 64 * 72 * 2)

__global__ __launch_bounds__(128) void attn_kernel(
    const __half* __restrict__ Q, int qld,
    const __half* __restrict__ KX,
    const __half* __restrict__ KL, int klld,
    __half* __restrict__ O)
{
    extern __shared__ __align__(16) __half sa[];
    __half* qs  = sa;
    __half* st0 = sa + 64 * 72;

    const int bh = blockIdx.x, b = bh >> 4, h = bh & 15;
    const int tid = threadIdx.x, wid = tid >> 5, lane = tid & 31;
    const int gid = lane >> 2, tg = lane & 3;
    const int row0 = wid * 16 + gid;

    {
        const __half2 sc2 = __floats2half2_rn(0.125f, 0.125f);
        const __half* Qb = Q + (size_t)(b * 64) * qld + h * 64;
        for (int i = tid; i < 2048; i += 128) {
            int r = i >> 5, cc = i & 31;
            __half2 v = *(const __half2*)(Qb + (size_t)r * qld + cc * 2);
            *(__half2*)(qs + r * 72 + cc * 2) = __hmul2(v, sc2);
        }
    }

    auto prefetch = [&](int c) {
        __half* ks = st0 + (c & 1) * 9216;
        __half* vv = ks + 4608;
        const __half* base;
        size_t ld;
        if (c < 32) { base = KX + ((size_t)(b * 2048 + c * 64)) * 4096 + h * 64; ld = 4096; }
        else        { base = KL + (size_t)(b * 64) * klld + h * 64;              ld = klld; }
#pragma unroll
        for (int i = 0; i < 4; i++) {
            int id = tid + (i << 7);
            int r = id >> 3, cc = id & 7;
            cpasync16(s2u(ks + r * 72 + cc * 8), base + (size_t)r * ld + cc * 8);
        }
#pragma unroll
        for (int i = 0; i < 4; i++) {
            int id = tid + (i << 7);
            int r = id >> 3, cc = id & 7;
            cpasync16(s2u(vv + r * 72 + cc * 8), base + (size_t)r * ld + 1024 + cc * 8);
        }
        asm volatile("cp.async.commit_group;" ::: "memory");
    };

    float m0 = -1e30f, m1 = -1e30f, l0 = 0.f, l1 = 0.f;
    float oa[8][4];
#pragma unroll
    for (int ni = 0; ni < 8; ni++)
#pragma unroll
        for (int j = 0; j < 4; j++) oa[ni][j] = 0.f;

    prefetch(0);

    for (int c = 0; c < 33; c++) {
        asm volatile("cp.async.wait_group 0;" ::: "memory");
        __syncthreads();
        if (c + 1 < 33) prefetch(c + 1);

        const __half* ks = st0 + (c & 1) * 9216;
        const uint32_t vbase = s2u(ks + 4608);

        float sc[8][4];
#pragma unroll
        for (int ni = 0; ni < 8; ni++)
#pragma unroll
            for (int j = 0; j < 4; j++) sc[ni][j] = 0.f;
#pragma unroll
        for (int kk = 0; kk < 4; kk++) {
            const int k0 = kk << 4;
            const __half* ap = qs + row0 * 72 + k0 + 2 * tg;
            uint32_t a0 = *(const uint32_t*)(ap);
            uint32_t a1 = *(const uint32_t*)(ap + 8 * 72);
            uint32_t a2 = *(const uint32_t*)(ap + 8);
            uint32_t a3 = *(const uint32_t*)(ap + 8 * 72 + 8);
#pragma unroll
            for (int ni = 0; ni < 8; ni++) {
                const __half* bp = ks + (ni * 8 + gid) * 72 + k0 + 2 * tg;
                uint32_t b0 = *(const uint32_t*)(bp);
                uint32_t b1 = *(const uint32_t*)(bp + 8);
                MMA16816(sc[ni], a0, a1, a2, a3, b0, b1);
            }
        }

        float mx0 = -1e30f, mx1 = -1e30f;
#pragma unroll
        for (int ni = 0; ni < 8; ni++) {
            mx0 = fmaxf(mx0, fmaxf(sc[ni][0], sc[ni][1]));
            mx1 = fmaxf(mx1, fmaxf(sc[ni][2], sc[ni][3]));
        }
        mx0 = fmaxf(mx0, __shfl_xor_sync(0xffffffffu, mx0, 1));
        mx0 = fmaxf(mx0, __shfl_xor_sync(0xffffffffu, mx0, 2));
        mx1 = fmaxf(mx1, __shfl_xor_sync(0xffffffffu, mx1, 1));
        mx1 = fmaxf(mx1, __shfl_xor_sync(0xffffffffu, mx1, 2));
        float mn0 = fmaxf(m0, mx0), mn1 = fmaxf(m1, mx1);
        float al0 = __expf(m0 - mn0), al1 = __expf(m1 - mn1);

        uint32_t pa[8][2];
        float ps0 = 0.f, ps1 = 0.f;
#pragma unroll
        for (int ni = 0; ni < 8; ni++) {
            float p0 = __expf(sc[ni][0] - mn0), p1 = __expf(sc[ni][1] - mn0);
            float p2 = __expf(sc[ni][2] - mn1), p3 = __expf(sc[ni][3] - mn1);
            ps0 += p0 + p1; ps1 += p2 + p3;
            __half2 h0 = __floats2half2_rn(p0, p1);
            __half2 h1 = __floats2half2_rn(p2, p3);
            pa[ni][0] = *(uint32_t*)&h0;
            pa[ni][1] = *(uint32_t*)&h1;
        }
        ps0 += __shfl_xor_sync(0xffffffffu, ps0, 1);
        ps0 += __shfl_xor_sync(0xffffffffu, ps0, 2);
        ps1 += __shfl_xor_sync(0xffffffffu, ps1, 1);
        ps1 += __shfl_xor_sync(0xffffffffu, ps1, 2);
        l0 = l0 * al0 + ps0; l1 = l1 * al1 + ps1;
        m0 = mn0; m1 = mn1;
#pragma unroll
        for (int ni = 0; ni < 8; ni++) {
            oa[ni][0] *= al0; oa[ni][1] *= al0;
            oa[ni][2] *= al1; oa[ni][3] *= al1;
        }

#pragma unroll
        for (int kk = 0; kk < 4; kk++) {
            uint32_t a0 = pa[2 * kk][0],     a1 = pa[2 * kk][1];
            uint32_t a2 = pa[2 * kk + 1][0], a3 = pa[2 * kk + 1][1];
            const uint32_t rowa = vbase + (((kk << 4) + (lane & 15)) * 72) * 2;
#pragma unroll
            for (int ni = 0; ni < 8; ni++) {
                uint32_t b0, b1;
                ldsm_x2_t(b0, b1, rowa + ni * 16);
                MMA16816(oa[ni], a0, a1, a2, a3, b0, b1);
            }
        }
    }

    float inv0 = 1.0f / l0, inv1 = 1.0f / l1;
    __half* Ob0 = O + ((size_t)(b * 64 + row0)) * 1024 + h * 64;
    __half* Ob1 = Ob0 + 8 * 1024;
#pragma unroll
    for (int ni = 0; ni < 8; ni++) {
        *(__half2*)(Ob0 + ni * 8 + 2 * tg) = __floats2half2_rn(oa[ni][0] * inv0, oa[ni][1] * inv0);
        *(__half2*)(Ob1 + ni * 8 + 2 * tg) = __floats2half2_rn(oa[ni][2] * inv1, oa[ni][3] * inv1);
    }
}

// ---------------------------------------------------------------------------
// Launch (R14 structure)
// ---------------------------------------------------------------------------
extern "C" void kernel_launch(void* const* d_in, const int* in_sizes, int n_in,
                              void* d_out, int out_size)
{
    const float* x       = (const float*)d_in[0];
    const float* latents = (const float*)d_in[1];
    const float* n1s     = (const float*)d_in[2];
    const float* n1b     = (const float*)d_in[3];
    const float* n2s     = (const float*)d_in[4];
    const float* n2b     = (const float*)d_in[5];
    const float* Wq      = (const float*)d_in[6];
    const float* Wkv     = (const float*)d_in[7];
    const float* Wo      = (const float*)d_in[8];
    const float* ffs     = (const float*)d_in[9];
    const float* ffb     = (const float*)d_in[10];
    const float* W1      = (const float*)d_in[11];
    const float* W2      = (const float*)d_in[12];
    const float* projw   = (const float*)d_in[13];
    const float* projb   = (const float*)d_in[14];
    const float* outs    = (const float*)d_in[15];
    const float* outb    = (const float*)d_in[16];
    float* out = (float*)d_out;

    __half *z, *kvX, *latH, *ltn, *qkvL, *o, *hbuf;
    __half *WaT, *WoT, *prT, *WkvTs, *W1T, *W2T;
    float *lat, *t2, *bkv;
    cudaGetSymbolAddress((void**)&z,    g_z);
    cudaGetSymbolAddress((void**)&kvX,  g_kvX);
    cudaGetSymbolAddress((void**)&lat,  g_lat);
    cudaGetSymbolAddress((void**)&latH, g_latH);
    cudaGetSymbolAddress((void**)&ltn,  g_ltn);
    cudaGetSymbolAddress((void**)&qkvL, g_qkvL);
    cudaGetSymbolAddress((void**)&o,    g_o);
    cudaGetSymbolAddress((void**)&t2,   g_t2);
    cudaGetSymbolAddress((void**)&hbuf, g_h);
    cudaGetSymbolAddress((void**)&WaT,  g_WaT);
    cudaGetSymbolAddress((void**)&WoT,  g_WoT);
    cudaGetSymbolAddress((void**)&prT,  g_prT);
    cudaGetSymbolAddress((void**)&WkvTs,g_WkvTs);
    cudaGetSymbolAddress((void**)&W1T,  g_W1T);
    cudaGetSymbolAddress((void**)&W2T,  g_W2T);
    cudaGetSymbolAddress((void**)&bkv,  g_bkv);

    cudaFuncSetAttribute(tc_gemm,     cudaFuncAttributeMaxDynamicSharedMemorySize, SMEM_TC);
    cudaFuncSetAttribute(attn_kernel, cudaFuncAttributeMaxDynamicSharedMemorySize, SMEM_ATT);

    dim3 tb(32, 8);

    // prep (minimal deps for kvX first)
    bcast_kernel<<<8192, 256>>>(latents, lat);
    lnw_kernel<<<16384, 128>>>(x, nullptr, z, nullptr, nullptr);
    transkv_kernel<<<dim3(64, 32, 2), tb>>>(Wkv, WkvTs, WaT, n1s);
    gemv_bias_kernel<<<1024, 128>>>(n1b, WaT, bkv);
    transpose_kernel<<<dim3(32, 32, 2), tb>>>(Wq, WaT, 1024, 1024, nullptr, WAT_LSTRIDE);

    // kvX for BOTH layers: [65536][4096]
    tc_gemm<<<dim3(32, 512), 128, SMEM_TC>>>(z, WkvTs,
        nullptr, bkv, nullptr, kvX, 65536, 4096, 1024, F_HALF);

    // remaining prep
    transpose_kernel<<<dim3(32, 32, 2), tb>>>(Wo, WoT, 1024, 1024, nullptr, 1048576);
    transpose_kernel<<<dim3(128,32, 2), tb>>>(W1, W1T, 1024, 4096, nullptr, 4194304);
    transpose_kernel<<<dim3(32,128, 2), tb>>>(W2, W2T, 4096, 1024, nullptr, 4194304);
    transpose_kernel<<<dim3(32, 32, 1), tb>>>(projw, prT, 1024, 1024, nullptr, 1048576);

    // ---- layers ----
    for (int i = 0; i < 2; i++) {
        lnw_kernel<<<512, 128>>>(lat, nullptr, ltn, n2s + i*1024, n2b + i*1024);

        // qkvL = ltn @ [Wq | Wkv]
        tc_gemm<<<dim3(24, 16), 128, SMEM_TC>>>(ltn, WaT + (size_t)i*WAT_LSTRIDE,
            nullptr, nullptr, nullptr, qkvL, 2048, 3072, 1024, F_HALF);

        attn_kernel<<<512, 128, SMEM_ATT>>>(qkvL, 3072, kvX + (size_t)i * 2048,
                                            qkvL + 1024, 3072, o);

        tc_gemm<<<dim3(8, 16), 128, SMEM_TC>>>(o, WoT + (size_t)i*1048576,
            lat, nullptr, lat, nullptr, 2048, 1024, 1024, F_RES);
        lnw_kernel<<<512, 128>>>(lat, nullptr, ltn, ffs + i*1024, ffb + i*1024);
        tc_gemm<<<dim3(32, 16), 128, SMEM_TC>>>(ltn, W1T + (size_t)i*4194304,
            nullptr, nullptr, nullptr, hbuf, 2048, 4096, 1024, F_GELU | F_HALF);
        tc_gemm<<<dim3(8, 16), 128, SMEM_TC>>>(hbuf, W2T + (size_t)i*4194304,
            lat, nullptr, lat, latH, 2048, 1024, 4096,
            F_RES | (i == 1 ? F_BOTH : 0));
    }

    // out = LN(lat @ proj_w + proj_b)
    tc_gemm<<<dim3(8, 16), 128, SMEM_TC>>>(latH, prT, nullptr, projb, t2, nullptr,
                                           2048, 1024, 1024, 0);
    lnw_kernel<<<512, 128>>>(t2, out, nullptr, outs, outb);
}

// round 17
// speedup vs baseline: 1.0156x; 1.0156x over previous
#include <cuda_runtime.h>
#include <cuda_fp16.h>
#include <cstdint>
#include <math.h>

// B=32, N1=2048, DIM=1024, HEADS=16, DH=64, NQ=64, L=2, FF=4096
#define F_RES  1
#define F_GELU 4
#define F_HALF 8
#define F_BOTH 16

// ---- scratch (device globals; allocation-free rule) ----
__device__ __half g_z   [67108864];   // 65536 x 1024  unit-LN(x)
__device__ __half g_kvX [268435456];  // 65536 x 4096  (both layers fused)
__device__ float  g_lat [2097152];
__device__ __half g_latH[2097152];
__device__ __half g_ltn [2097152];
__device__ __half g_qkvL[6291456];    // 2048 x 3072  (q | kvL)
__device__ __half g_o   [2097152];
__device__ float  g_t2  [2097152];
__device__ __half g_h   [8388608];    // 2048 x 4096
__device__ __half g_WaT [6291456];    // 2 x [3072][1024]
__device__ __half g_WoT [2097152];
__device__ __half g_prT [1048576];
__device__ __half g_WkvTs[4194304];   // [4096][1024] scaled by norm1_s (2 layers)
__device__ __half g_W1T [8388608];
__device__ __half g_W2T [8388608];
__device__ float  g_bkv [4096];

#define WAT_LSTRIDE 3145728

// ---------------------------------------------------------------------------
__device__ __forceinline__ uint32_t s2u(const void* p) {
    return (uint32_t)__cvta_generic_to_shared(p);
}
__device__ __forceinline__ void cpasync16(uint32_t dst, const void* src) {
    asm volatile("cp.async.cg.shared.global [%0], [%1], 16;" :: "r"(dst), "l"(src) : "memory");
}
__device__ __forceinline__ float gelu_f(float x) {
    float x3 = x * x * x;
    return 0.5f * x * (1.0f + tanhf(0.7978845608028654f * (x + 0.044715f * x3)));
}
#define MMA16816(c, a0, a1, a2, a3, b0, b1) \
    asm volatile( \
        "mma.sync.aligned.m16n8k16.row.col.f32.f16.f16.f32 " \
        "{%0,%1,%2,%3}, {%4,%5,%6,%7}, {%8,%9}, {%0,%1,%2,%3};" \
        : "+f"((c)[0]), "+f"((c)[1]), "+f"((c)[2]), "+f"((c)[3]) \
        : "r"(a0), "r"(a1), "r"(a2), "r"(a3), "r"(b0), "r"(b1))
__device__ __forceinline__ void ldsm_x2_t(uint32_t& r0, uint32_t& r1, uint32_t addr) {
    asm volatile("ldmatrix.sync.aligned.m8n8.x2.trans.shared.b16 {%0,%1}, [%2];"
                 : "=r"(r0), "=r"(r1) : "r"(addr));
}

// ---------------------------------------------------------------------------
// fp16 mma GEMM (frozen config, validated R11/R13/R14):
// BM=128, BN=128, BK=64, 4 warps (2x2), warp tile 64x64, m16n8k16,
// 3-stage cp.async pipeline, 2 CTAs/SM. K % 64 == 0, K >= 192.
// ---------------------------------------------------------------------------
#define AS_H      72
#define TILE_H    (128 * AS_H)
#define STG_H     (2 * TILE_H)
#define SMEM_TC   (3 * STG_H * 2)      // 110592

__device__ __forceinline__ void load_tile(
    __half* sm, int s, const __half* __restrict__ A, const __half* __restrict__ Bt,
    int K, size_t rowBase, size_t colBase, int t, int tid)
{
    __half* As = sm + s * STG_H;
    __half* Bs = As + TILE_H;
    const __half* Ag = A  + rowBase * K + t * 64;
    const __half* Bg = Bt + colBase * K + t * 64;
#pragma unroll
    for (int i = 0; i < 8; i++) {
        int ch = tid + (i << 7);
        int r = ch >> 3, c = ch & 7;
        cpasync16(s2u(As + r * AS_H + c * 8), Ag + (size_t)r * K + c * 8);
    }
#pragma unroll
    for (int i = 0; i < 8; i++) {
        int ch = tid + (i << 7);
        int r = ch >> 3, c = ch & 7;
        cpasync16(s2u(Bs + r * AS_H + c * 8), Bg + (size_t)r * K + c * 8);
    }
    asm volatile("cp.async.commit_group;" ::: "memory");
}

__global__ __launch_bounds__(128, 2) void tc_gemm(
    const __half* __restrict__ A, const __half* __restrict__ Bt,
    const float* __restrict__ Cin, const float* __restrict__ bias,
    float* __restrict__ C, __half* __restrict__ Ch,
    int M, int N, int K, int flags)
{
    extern __shared__ __align__(16) __half sm[];
    const int tid = threadIdx.x, wid = tid >> 5, lane = tid & 31;
    const int wm = wid & 1, wn = wid >> 1;
    const int gid = lane >> 2, tg = lane & 3;
    const size_t rowBase = (size_t)blockIdx.y * 128;
    const size_t colBase = (size_t)blockIdx.x * 128;

    float c[4][8][4];
#pragma unroll
    for (int mi = 0; mi < 4; mi++)
#pragma unroll
        for (int ni = 0; ni < 8; ni++)
#pragma unroll
            for (int k = 0; k < 4; k++) c[mi][ni][k] = 0.f;

    const int KT = K >> 6;
#pragma unroll
    for (int t = 0; t < 2; t++) load_tile(sm, t, A, Bt, K, rowBase, colBase, t, tid);

    for (int t = 0; t < KT; t++) {
        const int s = t % 3;
        asm volatile("cp.async.wait_group 1;" ::: "memory");
        __syncthreads();
        const int tp = t + 2;
        if (tp < KT) load_tile(sm, tp % 3, A, Bt, K, rowBase, colBase, tp, tid);

        const __half* As = sm + s * STG_H;
        const __half* Bs = As + TILE_H;
#pragma unroll
        for (int ks = 0; ks < 4; ks++) {
            const int k0 = ks << 4;
            uint32_t a[4][4], b[8][2];
#pragma unroll
            for (int mi = 0; mi < 4; mi++) {
                const __half* ap = As + (wm * 64 + mi * 16 + gid) * AS_H + k0 + 2 * tg;
                a[mi][0] = *(const uint32_t*)(ap);
                a[mi][1] = *(const uint32_t*)(ap + 8 * AS_H);
                a[mi][2] = *(const uint32_t*)(ap + 8);
                a[mi][3] = *(const uint32_t*)(ap + 8 * AS_H + 8);
            }
#pragma unroll
            for (int ni = 0; ni < 8; ni++) {
                const __half* bp = Bs + (wn * 64 + ni * 8 + gid) * AS_H + k0 + 2 * tg;
                b[ni][0] = *(const uint32_t*)(bp);
                b[ni][1] = *(const uint32_t*)(bp + 8);
            }
#pragma unroll
            for (int mi = 0; mi < 4; mi++)
#pragma unroll
                for (int ni = 0; ni < 8; ni++)
                    MMA16816(c[mi][ni], a[mi][0], a[mi][1], a[mi][2], a[mi][3],
                             b[ni][0], b[ni][1]);
        }
    }

    // epilogue
#pragma unroll
    for (int mi = 0; mi < 4; mi++) {
        const size_t r0 = rowBase + wm * 64 + mi * 16 + gid;
        const size_t r1 = r0 + 8;
#pragma unroll
        for (int ni = 0; ni < 8; ni++) {
            const size_t col = colBase + wn * 64 + ni * 8 + tg * 2;
            float v0 = c[mi][ni][0], v1 = c[mi][ni][1];
            float v2 = c[mi][ni][2], v3 = c[mi][ni][3];
            if (bias) {
                float b0 = bias[col], b1 = bias[col + 1];
                v0 += b0; v1 += b1; v2 += b0; v3 += b1;
            }
            if (flags & F_GELU) {
                v0 = gelu_f(v0); v1 = gelu_f(v1); v2 = gelu_f(v2); v3 = gelu_f(v3);
            }
            if (flags & F_RES) {
                const float2 p0 = *(const float2*)(Cin + r0 * N + col);
                const float2 p1 = *(const float2*)(Cin + r1 * N + col);
                v0 += p0.x; v1 += p0.y; v2 += p1.x; v3 += p1.y;
            }
            if (flags & F_HALF) {
                *(__half2*)(Ch + r0 * N + col) = __floats2half2_rn(v0, v1);
                *(__half2*)(Ch + r1 * N + col) = __floats2half2_rn(v2, v3);
            } else {
                *(float2*)(C + r0 * N + col) = make_float2(v0, v1);
                *(float2*)(C + r1 * N + col) = make_float2(v2, v3);
                if (flags & F_BOTH) {
                    *(__half2*)(Ch + r0 * N + col) = __floats2half2_rn(v0, v1);
                    *(__half2*)(Ch + r1 * N + col) = __floats2half2_rn(v2, v3);
                }
            }
        }
    }
}

// ---------------------------------------------------------------------------
__global__ void bcast_kernel(const float* __restrict__ lat0, float* __restrict__ lat)
{
    int i = blockIdx.x * 256 + threadIdx.x;
    lat[i] = lat0[i & 65535];
}

// ---------------------------------------------------------------------------
// Warp-per-row LayerNorm over 1024 cols. 128 threads = 4 rows/block.
// ---------------------------------------------------------------------------
__global__ __launch_bounds__(128) void lnw_kernel(
    const float* __restrict__ in, float* __restrict__ outF, __half* __restrict__ outH,
    const float* __restrict__ gs, const float* __restrict__ gb)
{
    const int row = blockIdx.x * 4 + (threadIdx.x >> 5);
    const int lane = threadIdx.x & 31;
    const float4* ip = (const float4*)(in + (size_t)row * 1024);

    float4 v[8];
    float s = 0.f, s2 = 0.f;
#pragma unroll
    for (int j = 0; j < 8; j++) {
        v[j] = ip[lane + 32 * j];
        s  += v[j].x + v[j].y + v[j].z + v[j].w;
        s2 += v[j].x*v[j].x + v[j].y*v[j].y + v[j].z*v[j].z + v[j].w*v[j].w;
    }
#pragma unroll
    for (int o = 16; o; o >>= 1) {
        s  += __shfl_xor_sync(0xffffffffu, s,  o);
        s2 += __shfl_xor_sync(0xffffffffu, s2, o);
    }
    const float mean = s * (1.0f / 1024.0f);
    const float inv  = rsqrtf(s2 * (1.0f / 1024.0f) - mean * mean + 1e-5f);

#pragma unroll
    for (int j = 0; j < 8; j++) {
        const int idx = lane + 32 * j;
        float4 ov;
        ov.x = (v[j].x - mean) * inv; ov.y = (v[j].y - mean) * inv;
        ov.z = (v[j].z - mean) * inv; ov.w = (v[j].w - mean) * inv;
        if (gs) {
            const float4 sv = ((const float4*)gs)[idx];
            const float4 bv = ((const float4*)gb)[idx];
            ov.x = ov.x * sv.x + bv.x; ov.y = ov.y * sv.y + bv.y;
            ov.z = ov.z * sv.z + bv.z; ov.w = ov.w * sv.w + bv.w;
        }
        if (outH) {
            __half2 h0 = __floats2half2_rn(ov.x, ov.y);
            __half2 h1 = __floats2half2_rn(ov.z, ov.w);
            uint2 pk;
            pk.x = *(uint32_t*)&h0; pk.y = *(uint32_t*)&h1;
            ((uint2*)(outH + (size_t)row * 1024))[idx] = pk;
        } else {
            ((float4*)(outF + (size_t)row * 1024))[idx] = ov;
        }
    }
}

// ---------------------------------------------------------------------------
// transpose (batched over gridDim.z): in[z][K][N] fp32 -> out half, with
// independent output layer stride (ostride elements per z).
// ---------------------------------------------------------------------------
__global__ void transpose_kernel(const float* __restrict__ in, __half* __restrict__ out,
                                 int K, int N, const float* __restrict__ sc,
                                 size_t ostride)
{
    __shared__ float t[32][33];
    const float* inz = in + (size_t)blockIdx.z * K * N;
    __half* outz = out + (size_t)blockIdx.z * ostride;
    const float* scz = sc ? sc + (size_t)blockIdx.z * K : nullptr;
    int nb = blockIdx.x * 32, kb = blockIdx.y * 32;
    int tx = threadIdx.x, ty = threadIdx.y;
#pragma unroll
    for (int i = 0; i < 4; i++) {
        int k = kb + ty + i * 8;
        float v = inz[(size_t)k * N + nb + tx];
        if (scz) v *= scz[k];
        t[ty + i * 8][tx] = v;
    }
    __syncthreads();
#pragma unroll
    for (int i = 0; i < 4; i++)
        outz[(size_t)(nb + ty + i * 8) * K + kb + tx] = __float2half(t[tx][ty + i * 8]);
}

// ---------------------------------------------------------------------------
// fused Wkv transpose: scaled -> WkvTs, plain -> WaT rows [1024, 3072)
// ---------------------------------------------------------------------------
__global__ void transkv_kernel(const float* __restrict__ in, __half* __restrict__ outS,
                               __half* __restrict__ outP, const float* __restrict__ sc)
{
    __shared__ float t[32][33];
    __shared__ float scs[32];
    const float* inz = in + (size_t)blockIdx.z * 2097152;
    __half* oS = outS + (size_t)blockIdx.z * 2097152;
    __half* oP = outP + (size_t)blockIdx.z * WAT_LSTRIDE + 1024 * 1024;
    int nb = blockIdx.x * 32, kb = blockIdx.y * 32;
    int tx = threadIdx.x, ty = threadIdx.y;
    if (ty == 0) scs[tx] = sc[blockIdx.z * 1024 + kb + tx];
#pragma unroll
    for (int i = 0; i < 4; i++) {
        int k = kb + ty + i * 8;
        t[ty + i * 8][tx] = inz[(size_t)k * 2048 + nb + tx];
    }
    __syncthreads();
#pragma unroll
    for (int i = 0; i < 4; i++) {
        size_t oi = (size_t)(nb + ty + i * 8) * 1024 + kb + tx;
        float v = t[tx][ty + i * 8];
        oP[oi] = __float2half(v);
        oS[oi] = __float2half(v * scs[tx]);
    }
}

// ---------------------------------------------------------------------------
// bias fold from WaT rows [1024,3072)
// ---------------------------------------------------------------------------
__global__ __launch_bounds__(128) void gemv_bias_kernel(
    const float* __restrict__ b, const __half* __restrict__ WaT,
    float* __restrict__ bias)
{
    const int j = blockIdx.x * 4 + (threadIdx.x >> 5);
    const int lane = threadIdx.x & 31;
    const int layer = j >> 11, r = j & 2047;
    const float* bz = b + layer * 1024;
    const __half* wp = WaT + (size_t)layer * WAT_LSTRIDE + (size_t)(1024 + r) * 1024;

    float s = 0.f;
#pragma unroll
    for (int i = 0; i < 4; i++) {
        uint4 w8 = ((const uint4*)wp)[lane + 32 * i];
        const __half2* hw = (const __half2*)&w8;
        const int k0 = (lane + 32 * i) * 8;
#pragma unroll
        for (int p = 0; p < 4; p++) {
            float2 wf = __half22float2(hw[p]);
            s += wf.x * bz[k0 + 2 * p] + wf.y * bz[k0 + 2 * p + 1];
        }
    }
#pragma unroll
    for (int o = 16; o; o >>= 1) s += __shfl_xor_sync(0xffffffffu, s, o);
    if (lane == 0) bias[j] = s;
}

// ---------------------------------------------------------------------------
// Attention (validated R14): cp.async double-buffered K/V + ldmatrix.trans
// ---------------------------------------------------------------------------
#define SMEM_ATT (5 * 64 * 72 * 2)

__global__ __launch_bounds__(128) void attn_kernel(
    const __half* __restrict__ Q, int qld,
    const __half* __restrict__ KX,
    const __half* __restrict__ KL, int klld,
    __half* __restrict__ O)
{
    extern __shared__ __align__(16) __half sa[];
    __half* qs  = sa;
    __half* st0 = sa + 64 * 72;

    const int bh = blockIdx.x, b = bh >> 4, h = bh & 15;
    const int tid = threadIdx.x, wid = tid >> 5, lane = tid & 31;
    const int gid = lane >> 2, tg = lane & 3;
    const int row0 = wid * 16 + gid;

    {
        const __half2 sc2 = __floats2half2_rn(0.125f, 0.125f);
        const __half* Qb = Q + (size_t)(b * 64) * qld + h * 64;
        for (int i = tid; i < 2048; i += 128) {
            int r = i >> 5, cc = i & 31;
            __half2 v = *(const __half2*)(Qb + (size_t)r * qld + cc * 2);
            *(__half2*)(qs + r * 72 + cc * 2) = __hmul2(v, sc2);
        }
    }

    auto prefetch = [&](int c) {
        __half* ks = st0 + (c & 1) * 9216;
        __half* vv = ks + 4608;
        const __half* base;
        size_t ld;
        if (c < 32) { base = KX + ((size_t)(b * 2048 + c * 64)) * 4096 + h * 64; ld = 4096; }
        else        { base = KL + (size_t)(b * 64) * klld + h * 64;              ld = klld; }
#pragma unroll
        for (int i = 0; i < 4; i++) {
            int id = tid + (i << 7);
            int r = id >> 3, cc = id & 7;
            cpasync16(s2u(ks + r * 72 + cc * 8), base + (size_t)r * ld + cc * 8);
        }
#pragma unroll
        for (int i = 0; i < 4; i++) {
            int id = tid + (i << 7);
            int r = id >> 3, cc = id & 7;
            cpasync16(s2u(vv + r * 72 + cc * 8), base + (size_t)r * ld + 1024 + cc * 8);
        }
        asm volatile("cp.async.commit_group;" ::: "memory");
    };

    float m0 = -1e30f, m1 = -1e30f, l0 = 0.f, l1 = 0.f;
    float oa[8][4];
#pragma unroll
    for (int ni = 0; ni < 8; ni++)
#pragma unroll
        for (int j = 0; j < 4; j++) oa[ni][j] = 0.f;

    prefetch(0);

    for (int c = 0; c < 33; c++) {
        asm volatile("cp.async.wait_group 0;" ::: "memory");
        __syncthreads();
        if (c + 1 < 33) prefetch(c + 1);

        const __half* ks = st0 + (c & 1) * 9216;
        const uint32_t vbase = s2u(ks + 4608);

        float sc[8][4];
#pragma unroll
        for (int ni = 0; ni < 8; ni++)
#pragma unroll
            for (int j = 0; j < 4; j++) sc[ni][j] = 0.f;
#pragma unroll
        for (int kk = 0; kk < 4; kk++) {
            const int k0 = kk << 4;
            const __half* ap = qs + row0 * 72 + k0 + 2 * tg;
            uint32_t a0 = *(const uint32_t*)(ap);
            uint32_t a1 = *(const uint32_t*)(ap + 8 * 72);
            uint32_t a2 = *(const uint32_t*)(ap + 8);
            uint32_t a3 = *(const uint32_t*)(ap + 8 * 72 + 8);
#pragma unroll
            for (int ni = 0; ni < 8; ni++) {
                const __half* bp = ks + (ni * 8 + gid) * 72 + k0 + 2 * tg;
                uint32_t b0 = *(const uint32_t*)(bp);
                uint32_t b1 = *(const uint32_t*)(bp + 8);
                MMA16816(sc[ni], a0, a1, a2, a3, b0, b1);
            }
        }

        float mx0 = -1e30f, mx1 = -1e30f;
#pragma unroll
        for (int ni = 0; ni < 8; ni++) {
            mx0 = fmaxf(mx0, fmaxf(sc[ni][0], sc[ni][1]));
            mx1 = fmaxf(mx1, fmaxf(sc[ni][2], sc[ni][3]));
        }
        mx0 = fmaxf(mx0, __shfl_xor_sync(0xffffffffu, mx0, 1));
        mx0 = fmaxf(mx0, __shfl_xor_sync(0xffffffffu, mx0, 2));
        mx1 = fmaxf(mx1, __shfl_xor_sync(0xffffffffu, mx1, 1));
        mx1 = fmaxf(mx1, __shfl_xor_sync(0xffffffffu, mx1, 2));
        float mn0 = fmaxf(m0, mx0), mn1 = fmaxf(m1, mx1);
        float al0 = __expf(m0 - mn0), al1 = __expf(m1 - mn1);

        uint32_t pa[8][2];
        float ps0 = 0.f, ps1 = 0.f;
#pragma unroll
        for (int ni = 0; ni < 8; ni++) {
            float p0 = __expf(sc[ni][0] - mn0), p1 = __expf(sc[ni][1] - mn0);
            float p2 = __expf(sc[ni][2] - mn1), p3 = __expf(sc[ni][3] - mn1);
            ps0 += p0 + p1; ps1 += p2 + p3;
            __half2 h0 = __floats2half2_rn(p0, p1);
            __half2 h1 = __floats2half2_rn(p2, p3);
            pa[ni][0] = *(uint32_t*)&h0;
            pa[ni][1] = *(uint32_t*)&h1;
        }
        ps0 += __shfl_xor_sync(0xffffffffu, ps0, 1);
        ps0 += __shfl_xor_sync(0xffffffffu, ps0, 2);
        ps1 += __shfl_xor_sync(0xffffffffu, ps1, 1);
        ps1 += __shfl_xor_sync(0xffffffffu, ps1, 2);
        l0 = l0 * al0 + ps0; l1 = l1 * al1 + ps1;
        m0 = mn0; m1 = mn1;
#pragma unroll
        for (int ni = 0; ni < 8; ni++) {
            oa[ni][0] *= al0; oa[ni][1] *= al0;
            oa[ni][2] *= al1; oa[ni][3] *= al1;
        }

#pragma unroll
        for (int kk = 0; kk < 4; kk++) {
            uint32_t a0 = pa[2 * kk][0],     a1 = pa[2 * kk][1];
            uint32_t a2 = pa[2 * kk + 1][0], a3 = pa[2 * kk + 1][1];
            const uint32_t rowa = vbase + (((kk << 4) + (lane & 15)) * 72) * 2;
#pragma unroll
            for (int ni = 0; ni < 8; ni++) {
                uint32_t b0, b1;
                ldsm_x2_t(b0, b1, rowa + ni * 16);
                MMA16816(oa[ni], a0, a1, a2, a3, b0, b1);
            }
        }
    }

    float inv0 = 1.0f / l0, inv1 = 1.0f / l1;
    __half* Ob0 = O + ((size_t)(b * 64 + row0)) * 1024 + h * 64;
    __half* Ob1 = Ob0 + 8 * 1024;
#pragma unroll
    for (int ni = 0; ni < 8; ni++) {
        *(__half2*)(Ob0 + ni * 8 + 2 * tg) = __floats2half2_rn(oa[ni][0] * inv0, oa[ni][1] * inv0);
        *(__half2*)(Ob1 + ni * 8 + 2 * tg) = __floats2half2_rn(oa[ni][2] * inv1, oa[ni][3] * inv1);
    }
}

// ---------------------------------------------------------------------------
// Launch (R14 structure)
// ---------------------------------------------------------------------------
extern "C" void kernel_launch(void* const* d_in, const int* in_sizes, int n_in,
                              void* d_out, int out_size)
{
    const float* x       = (const float*)d_in[0];
    const float* latents = (const float*)d_in[1];
    const float* n1s     = (const float*)d_in[2];
    const float* n1b     = (const float*)d_in[3];
    const float* n2s     = (const float*)d_in[4];
    const float* n2b     = (const float*)d_in[5];
    const float* Wq      = (const float*)d_in[6];
    const float* Wkv     = (const float*)d_in[7];
    const float* Wo      = (const float*)d_in[8];
    const float* ffs     = (const float*)d_in[9];
    const float* ffb     = (const float*)d_in[10];
    const float* W1      = (const float*)d_in[11];
    const float* W2      = (const float*)d_in[12];
    const float* projw   = (const float*)d_in[13];
    const float* projb   = (const float*)d_in[14];
    const float* outs    = (const float*)d_in[15];
    const float* outb    = (const float*)d_in[16];
    float* out = (float*)d_out;

    __half *z, *kvX, *latH, *ltn, *qkvL, *o, *hbuf;
    __half *WaT, *WoT, *prT, *WkvTs, *W1T, *W2T;
    float *lat, *t2, *bkv;
    cudaGetSymbolAddress((void**)&z,    g_z);
    cudaGetSymbolAddress((void**)&kvX,  g_kvX);
    cudaGetSymbolAddress((void**)&lat,  g_lat);
    cudaGetSymbolAddress((void**)&latH, g_latH);
    cudaGetSymbolAddress((void**)&ltn,  g_ltn);
    cudaGetSymbolAddress((void**)&qkvL, g_qkvL);
    cudaGetSymbolAddress((void**)&o,    g_o);
    cudaGetSymbolAddress((void**)&t2,   g_t2);
    cudaGetSymbolAddress((void**)&hbuf, g_h);
    cudaGetSymbolAddress((void**)&WaT,  g_WaT);
    cudaGetSymbolAddress((void**)&WoT,  g_WoT);
    cudaGetSymbolAddress((void**)&prT,  g_prT);
    cudaGetSymbolAddress((void**)&WkvTs,g_WkvTs);
    cudaGetSymbolAddress((void**)&W1T,  g_W1T);
    cudaGetSymbolAddress((void**)&W2T,  g_W2T);
    cudaGetSymbolAddress((void**)&bkv,  g_bkv);

    cudaFuncSetAttribute(tc_gemm,     cudaFuncAttributeMaxDynamicSharedMemorySize, SMEM_TC);
    cudaFuncSetAttribute(attn_kernel, cudaFuncAttributeMaxDynamicSharedMemorySize, SMEM_ATT);

    dim3 tb(32, 8);

    // prep (minimal deps for kvX first)
    bcast_kernel<<<8192, 256>>>(latents, lat);
    lnw_kernel<<<16384, 128>>>(x, nullptr, z, nullptr, nullptr);
    transkv_kernel<<<dim3(64, 32, 2), tb>>>(Wkv, WkvTs, WaT, n1s);
    gemv_bias_kernel<<<1024, 128>>>(n1b, WaT, bkv);
    transpose_kernel<<<dim3(32, 32, 2), tb>>>(Wq, WaT, 1024, 1024, nullptr, WAT_LSTRIDE);

    // kvX for BOTH layers: [65536][4096]
    tc_gemm<<<dim3(32, 512), 128, SMEM_TC>>>(z, WkvTs,
        nullptr, bkv, nullptr, kvX, 65536, 4096, 1024, F_HALF);

    // remaining prep
    transpose_kernel<<<dim3(32, 32, 2), tb>>>(Wo, WoT, 1024, 1024, nullptr, 1048576);
    transpose_kernel<<<dim3(128,32, 2), tb>>>(W1, W1T, 1024, 4096, nullptr, 4194304);
    transpose_kernel<<<dim3(32,128, 2), tb>>>(W2, W2T, 4096, 1024, nullptr, 4194304);
    transpose_kernel<<<dim3(32, 32, 1), tb>>>(projw, prT, 1024, 1024, nullptr, 1048576);

    // ---- layers ----
    for (int i = 0; i < 2; i++) {
        lnw_kernel<<<512, 128>>>(lat, nullptr, ltn, n2s + i*1024, n2b + i*1024);

        // qkvL = ltn @ [Wq | Wkv]
        tc_gemm<<<dim3(24, 16), 128, SMEM_TC>>>(ltn, WaT + (size_t)i*WAT_LSTRIDE,
            nullptr, nullptr, nullptr, qkvL, 2048, 3072, 1024, F_HALF);

        attn_kernel<<<512, 128, SMEM_ATT>>>(qkvL, 3072, kvX + (size_t)i * 2048,
                                            qkvL + 1024, 3072, o);

        tc_gemm<<<dim3(8, 16), 128, SMEM_TC>>>(o, WoT + (size_t)i*1048576,
            lat, nullptr, lat, nullptr, 2048, 1024, 1024, F_RES);
        lnw_kernel<<<512, 128>>>(lat, nullptr, ltn, ffs + i*1024, ffb + i*1024);
        tc_gemm<<<dim3(32, 16), 128, SMEM_TC>>>(ltn, W1T + (size_t)i*4194304,
            nullptr, nullptr, nullptr, hbuf, 2048, 4096, 1024, F_GELU | F_HALF);
        tc_gemm<<<dim3(8, 16), 128, SMEM_TC>>>(hbuf, W2T + (size_t)i*4194304,
            lat, nullptr, lat, latH, 2048, 1024, 4096,
            F_RES | (i == 1 ? F_BOTH : 0));
    }

    // out = LN(lat @ proj_w + proj_b)
    tc_gemm<<<dim3(8, 16), 128, SMEM_TC>>>(latH, prT, nullptr, projb, t2, nullptr,
                                           2048, 1024, 1024, 0);
    lnw_kernel<<<512, 128>>>(t2, out, nullptr, outs, outb);
}